// round 15
// baseline (speedup 1.0000x reference)
#include <cuda_runtime.h>
#include <cuda_fp16.h>
#include <cstdint>

#define NN 100000
#define INF_ 128
#define OUTF 64
#define NE 1600000
#define NCHUNK ((NN + 511) / 512)   // 196

// Static device scratch (allocation-free per harness rules).
// g_counts is zero at module load; pull restores it to zero every call,
// so hist can run without a zeroing pass (and concurrently with the GEMM).
__device__ __half g_support_h[(size_t)NN * OUTF];  // 12.8 MB (fp16 gather path)
__device__ int    g_counts[NN];
__device__ int    g_rowstart[NN];
__device__ int    g_cursor[NN];
__device__ int    g_chunksum[NCHUNK];
__device__ int2   g_packed[NE];                    // 12.8 MB (col, val-bits) by row

// ---------------------------------------------------------------------------
// support = X @ W.  Tiled fp32 SIMT GEMM; epilogue stores fp16.
// (Runs concurrently with the edge-build chain on another stream.)
// ---------------------------------------------------------------------------
__global__ __launch_bounds__(256, 2)
void gemm_kernel(const float* __restrict__ x, const float* __restrict__ w, int n) {
    __shared__ float xs[64][132];
    __shared__ float ws[128][68];

    const int tid  = threadIdx.x;
    const int brow = blockIdx.x * 64;

#pragma unroll
    for (int it = 0; it < 8; it++) {
        int i = tid + it * 256;
        int k = i >> 4;
        int c = (i & 15) << 2;
        float4 v = *(const float4*)&w[k * OUTF + c];
        *(float4*)&ws[k][c] = v;
    }
#pragma unroll
    for (int it = 0; it < 8; it++) {
        int i = tid + it * 256;
        int r = i >> 5;
        int k = (i & 31) << 2;
        int grow = brow + r;
        float4 v = make_float4(0.f, 0.f, 0.f, 0.f);
        if (grow < n) v = *(const float4*)&x[(size_t)grow * INF_ + k];
        *(float4*)&xs[r][k] = v;
    }
    __syncthreads();

    const int r0 = (tid >> 4) << 2;
    const int c0 = (tid & 15) << 2;

    float acc[4][4] = {};
#pragma unroll 4
    for (int k = 0; k < 128; k++) {
        float a0 = xs[r0 + 0][k];
        float a1 = xs[r0 + 1][k];
        float a2 = xs[r0 + 2][k];
        float a3 = xs[r0 + 3][k];
        float4 b = *(float4*)&ws[k][c0];
        acc[0][0] += a0 * b.x; acc[0][1] += a0 * b.y; acc[0][2] += a0 * b.z; acc[0][3] += a0 * b.w;
        acc[1][0] += a1 * b.x; acc[1][1] += a1 * b.y; acc[1][2] += a1 * b.z; acc[1][3] += a1 * b.w;
        acc[2][0] += a2 * b.x; acc[2][1] += a2 * b.y; acc[2][2] += a2 * b.z; acc[2][3] += a2 * b.w;
        acc[3][0] += a3 * b.x; acc[3][1] += a3 * b.y; acc[3][2] += a3 * b.z; acc[3][3] += a3 * b.w;
    }

#pragma unroll
    for (int i = 0; i < 4; i++) {
        int grow = brow + r0 + i;
        if (grow < n) {
            __half2 h0 = __floats2half2_rn(acc[i][0], acc[i][1]);
            __half2 h1 = __floats2half2_rn(acc[i][2], acc[i][3]);
            uint2 u = make_uint2(*(unsigned*)&h0, *(unsigned*)&h1);
            *(uint2*)&g_support_h[(size_t)grow * OUTF + c0] = u;
        }
    }
}

// ---------------------------------------------------------------------------
// Build phase: counting sort of edges by destination row.
// hist/fill process 4 edges per thread (vector loads, 4 independent atomics).
// ---------------------------------------------------------------------------
__global__ void hist_kernel(const int4* __restrict__ erow4) {
    int i = blockIdx.x * blockDim.x + threadIdx.x;
    if (i < NE / 4) {
        int4 r = __ldg(&erow4[i]);
        atomicAdd(&g_counts[r.x], 1);
        atomicAdd(&g_counts[r.y], 1);
        atomicAdd(&g_counts[r.z], 1);
        atomicAdd(&g_counts[r.w], 1);
    }
}

// S1: per-chunk (512) reduction of counts -> g_chunksum[b]
__global__ __launch_bounds__(512)
void scan1_kernel() {
    __shared__ int s[512];
    int t = threadIdx.x, b = blockIdx.x;
    int i = b * 512 + t;
    s[t] = (i < NN) ? g_counts[i] : 0;
    __syncthreads();
#pragma unroll
    for (int off = 256; off > 0; off >>= 1) {
        if (t < off) s[t] += s[t + off];
        __syncthreads();
    }
    if (t == 0) g_chunksum[b] = s[0];
}

// S3: per-chunk exclusive scan; chunk base computed inline via warp reduction
// over chunksum[0..b-1] (196 tiny L2-hot loads).
__global__ __launch_bounds__(512)
void scan3_kernel() {
    __shared__ int s[512];
    __shared__ int sbase[1];
    int t = threadIdx.x, b = blockIdx.x;
    int i = b * 512 + t;
    int v = (i < NN) ? g_counts[i] : 0;
    s[t] = v;

    if (t < 32) {
        int part = 0;
        for (int c = t; c < b; c += 32) part += g_chunksum[c];
#pragma unroll
        for (int off = 16; off > 0; off >>= 1)
            part += __shfl_xor_sync(0xffffffffu, part, off);
        if (t == 0) sbase[0] = part;
    }
    __syncthreads();
#pragma unroll
    for (int off = 1; off < 512; off <<= 1) {
        int a = (t >= off) ? s[t - off] : 0;
        __syncthreads();
        s[t] += a;
        __syncthreads();
    }
    if (i < NN) {
        int excl = s[t] - v + sbase[0];
        g_rowstart[i] = excl;
        g_cursor[i]   = excl;
    }
}

__global__ void fill_kernel(const int4* __restrict__ erow4, const int4* __restrict__ ecol4,
                            const float4* __restrict__ evals4) {
    int i = blockIdx.x * blockDim.x + threadIdx.x;
    if (i < NE / 4) {
        int4   r = __ldg(&erow4[i]);
        int4   c = __ldg(&ecol4[i]);
        float4 v = __ldg(&evals4[i]);
        int p0 = atomicAdd(&g_cursor[r.x], 1);
        int p1 = atomicAdd(&g_cursor[r.y], 1);
        int p2 = atomicAdd(&g_cursor[r.z], 1);
        int p3 = atomicAdd(&g_cursor[r.w], 1);
        g_packed[p0] = make_int2(c.x, __float_as_int(v.x));
        g_packed[p1] = make_int2(c.y, __float_as_int(v.y));
        g_packed[p2] = make_int2(c.z, __float_as_int(v.z));
        g_packed[p3] = make_int2(c.w, __float_as_int(v.w));
    }
}

// ---------------------------------------------------------------------------
// Pull: 2 rows per warp, 16 lanes per row, 4 features (8B fp16) per lane.
// Per edge the 16-lane group reads 128B = ONE L2 line.
// fp32 accumulate, plain float4 store (bias fused, no atomics).
// After reading its count, each warp zeroes it (restores the zero invariant
// for the next call's hist, eliminating the zeroing kernel).
// ---------------------------------------------------------------------------
__global__ __launch_bounds__(256)
void pull_kernel(const float* __restrict__ bias, float* __restrict__ out) {
    int warp = (blockIdx.x * 256 + threadIdx.x) >> 5;
    if (warp >= NN / 2) return;
    int lane = threadIdx.x & 31;
    int half = lane >> 4;                // 0 or 1
    int sub  = lane & 15;                // 0..15

    const int row   = warp * 2 + half;
    const int start = g_rowstart[row];
    const int len   = g_counts[row];
    __syncwarp();
    if (sub == 0) g_counts[row] = 0;     // restore invariant (one writer/row)

    const int lenm  = max(len, __shfl_xor_sync(0xffffffffu, len, 16));
    const int2* __restrict__ plist = g_packed + start;
    const int fo = sub * 4;
    const int hb = half << 4;

    float4 acc = *(const float4*)&bias[fo];

    for (int base = 0; base < lenm; base += 16) {
        int m  = len - base;
        int mm = lenm - base; mm = mm < 16 ? mm : 16;
        int2 p = make_int2(0, 0);
        if (sub < m) p = plist[base + sub];

        int j = 0;
        for (; j + 8 <= mm; j += 8) {
            int cc[8];
            uint2 rr[8];
            float vv[8];
#pragma unroll
            for (int k = 0; k < 8; k++)
                cc[k] = __shfl_sync(0xffffffffu, p.x, hb + j + k);
#pragma unroll
            for (int k = 0; k < 8; k++)
                rr[k] = *(const uint2*)&g_support_h[(size_t)cc[k] * OUTF + fo];
#pragma unroll
            for (int k = 0; k < 8; k++)
                vv[k] = __int_as_float(__shfl_sync(0xffffffffu, p.y, hb + j + k));
#pragma unroll
            for (int k = 0; k < 8; k++) {
                float2 a = __half22float2(*(__half2*)&rr[k].x);
                float2 b = __half22float2(*(__half2*)&rr[k].y);
                acc.x += a.x * vv[k]; acc.y += a.y * vv[k];
                acc.z += b.x * vv[k]; acc.w += b.y * vv[k];
            }
        }
        for (; j + 4 <= mm; j += 4) {
            int cc[4];
            uint2 rr[4];
            float vv[4];
#pragma unroll
            for (int k = 0; k < 4; k++)
                cc[k] = __shfl_sync(0xffffffffu, p.x, hb + j + k);
#pragma unroll
            for (int k = 0; k < 4; k++)
                rr[k] = *(const uint2*)&g_support_h[(size_t)cc[k] * OUTF + fo];
#pragma unroll
            for (int k = 0; k < 4; k++)
                vv[k] = __int_as_float(__shfl_sync(0xffffffffu, p.y, hb + j + k));
#pragma unroll
            for (int k = 0; k < 4; k++) {
                float2 a = __half22float2(*(__half2*)&rr[k].x);
                float2 b = __half22float2(*(__half2*)&rr[k].y);
                acc.x += a.x * vv[k]; acc.y += a.y * vv[k];
                acc.z += b.x * vv[k]; acc.w += b.y * vv[k];
            }
        }
        for (; j < mm; j++) {
            int   c = __shfl_sync(0xffffffffu, p.x, hb + j);
            float v = __int_as_float(__shfl_sync(0xffffffffu, p.y, hb + j));
            uint2 rv = *(const uint2*)&g_support_h[(size_t)c * OUTF + fo];
            float2 a = __half22float2(*(__half2*)&rv.x);
            float2 b = __half22float2(*(__half2*)&rv.y);
            acc.x += a.x * v; acc.y += a.y * v; acc.z += b.x * v; acc.w += b.y * v;
        }
    }

    *(float4*)&out[(size_t)row * OUTF + fo] = acc;
}

// ---------------------------------------------------------------------------
// Forked-capture schedule:
//   default stream:  gemm ─────────────┐
//   build stream:    hist→scan1→scan3→fill ─┴→ pull   (join via events)
// ---------------------------------------------------------------------------
static cudaStream_t s_build = nullptr;
static cudaEvent_t  ev_fork = nullptr;
static cudaEvent_t  ev_join = nullptr;

extern "C" void kernel_launch(void* const* d_in, const int* in_sizes, int n_in,
                              void* d_out, int out_size) {
    const float* x     = (const float*)d_in[0];   // [100000,128]
    const float* w     = (const float*)d_in[1];   // [128,64]
    const float* bias  = (const float*)d_in[2];   // [64]
    const int*   erow  = (const int*)  d_in[3];   // [1.6M]
    const int*   ecol  = (const int*)  d_in[4];   // [1.6M]
    const float* evals = (const float*)d_in[5];   // [1.6M]
    float* out = (float*)d_out;                   // [100000,64]

    const int n = in_sizes[0] / INF_;             // 100000

    if (s_build == nullptr) {
        cudaStreamCreateWithFlags(&s_build, cudaStreamNonBlocking);
        cudaEventCreateWithFlags(&ev_fork, cudaEventDisableTiming);
        cudaEventCreateWithFlags(&ev_join, cudaEventDisableTiming);
    }

    // Fork: build stream joins the capture DAG after current point
    cudaEventRecord(ev_fork, 0);
    cudaStreamWaitEvent(s_build, ev_fork, 0);

    // Default stream: support = X @ W (fp32 compute, fp16 store)
    gemm_kernel<<<(n + 63) / 64, 256>>>(x, w, n);

    // Build stream: counting sort of edges by destination row
    hist_kernel<<<(NE / 4 + 255) / 256, 256, 0, s_build>>>((const int4*)erow);
    scan1_kernel<<<NCHUNK, 512, 0, s_build>>>();
    scan3_kernel<<<NCHUNK, 512, 0, s_build>>>();
    fill_kernel<<<(NE / 4 + 255) / 256, 256, 0, s_build>>>((const int4*)erow,
                                                           (const int4*)ecol,
                                                           (const float4*)evals);

    // Join: pull needs both gemm (default) and fill (s_build)
    cudaEventRecord(ev_join, s_build);
    cudaStreamWaitEvent(0, ev_join, 0);

    // Pull: out[row] = bias + sum(support[col] * val)
    {
        int warps = NN / 2;                        // 50000
        int blocks = (warps * 32 + 255) / 256;     // 6250
        pull_kernel<<<blocks, 256>>>(bias, out);
    }
}

// round 16
// speedup vs baseline: 1.0213x; 1.0213x over previous
#include <cuda_runtime.h>
#include <cuda_fp16.h>
#include <cstdint>

#define NN 100000
#define INF_ 128
#define OUTF 64
#define NE 1600000
#define CAP 24   // per-row bucket slots; Poisson(16) tail spills to g_ovf

// Static device scratch (allocation-free per harness rules).
// g_cursor is zero at module load; pull restores it to zero every call.
__device__ __half g_support_h[(size_t)NN * OUTF];  // 12.8 MB (fp16 gather path)
__device__ int    g_cursor[NN];                    // per-row count/bump cursor
__device__ int2   g_bucket[(size_t)NN * CAP];      // 19.2 MB (col, val-bits)
__device__ int    g_ovf_cnt;
__device__ int3   g_ovf[NE];                       // spill (row, col, val-bits)

// ---------------------------------------------------------------------------
// support = X @ W.  Tiled fp32 SIMT GEMM; epilogue stores fp16.
// Also zeroes the spill counter (fill launches after, in stream order).
// ---------------------------------------------------------------------------
__global__ __launch_bounds__(256, 2)
void gemm_kernel(const float* __restrict__ x, const float* __restrict__ w, int n) {
    __shared__ float xs[64][132];
    __shared__ float ws[128][68];

    const int tid  = threadIdx.x;
    const int brow = blockIdx.x * 64;

    if (blockIdx.x == 0 && tid == 0) g_ovf_cnt = 0;

#pragma unroll
    for (int it = 0; it < 8; it++) {
        int i = tid + it * 256;
        int k = i >> 4;
        int c = (i & 15) << 2;
        float4 v = *(const float4*)&w[k * OUTF + c];
        *(float4*)&ws[k][c] = v;
    }
#pragma unroll
    for (int it = 0; it < 8; it++) {
        int i = tid + it * 256;
        int r = i >> 5;
        int k = (i & 31) << 2;
        int grow = brow + r;
        float4 v = make_float4(0.f, 0.f, 0.f, 0.f);
        if (grow < n) v = *(const float4*)&x[(size_t)grow * INF_ + k];
        *(float4*)&xs[r][k] = v;
    }
    __syncthreads();

    const int r0 = (tid >> 4) << 2;
    const int c0 = (tid & 15) << 2;

    float acc[4][4] = {};
#pragma unroll 4
    for (int k = 0; k < 128; k++) {
        float a0 = xs[r0 + 0][k];
        float a1 = xs[r0 + 1][k];
        float a2 = xs[r0 + 2][k];
        float a3 = xs[r0 + 3][k];
        float4 b = *(float4*)&ws[k][c0];
        acc[0][0] += a0 * b.x; acc[0][1] += a0 * b.y; acc[0][2] += a0 * b.z; acc[0][3] += a0 * b.w;
        acc[1][0] += a1 * b.x; acc[1][1] += a1 * b.y; acc[1][2] += a1 * b.z; acc[1][3] += a1 * b.w;
        acc[2][0] += a2 * b.x; acc[2][1] += a2 * b.y; acc[2][2] += a2 * b.z; acc[2][3] += a2 * b.w;
        acc[3][0] += a3 * b.x; acc[3][1] += a3 * b.y; acc[3][2] += a3 * b.z; acc[3][3] += a3 * b.w;
    }

#pragma unroll
    for (int i = 0; i < 4; i++) {
        int grow = brow + r0 + i;
        if (grow < n) {
            __half2 h0 = __floats2half2_rn(acc[i][0], acc[i][1]);
            __half2 h1 = __floats2half2_rn(acc[i][2], acc[i][3]);
            uint2 u = make_uint2(*(unsigned*)&h0, *(unsigned*)&h1);
            *(uint2*)&g_support_h[(size_t)grow * OUTF + c0] = u;
        }
    }
}

// ---------------------------------------------------------------------------
// Fill: one pass, no hist/scan.  4 edges per thread, 4 independent atomics.
// pos < CAP -> bucket store; else spill list (rare, Poisson tail).
// ---------------------------------------------------------------------------
__global__ void fill_kernel(const int4* __restrict__ erow4, const int4* __restrict__ ecol4,
                            const float4* __restrict__ evals4) {
    int i = blockIdx.x * blockDim.x + threadIdx.x;
    if (i < NE / 4) {
        int4   r = __ldg(&erow4[i]);
        int4   c = __ldg(&ecol4[i]);
        float4 v = __ldg(&evals4[i]);
        int p0 = atomicAdd(&g_cursor[r.x], 1);
        int p1 = atomicAdd(&g_cursor[r.y], 1);
        int p2 = atomicAdd(&g_cursor[r.z], 1);
        int p3 = atomicAdd(&g_cursor[r.w], 1);
        if (p0 < CAP) g_bucket[(size_t)r.x * CAP + p0] = make_int2(c.x, __float_as_int(v.x));
        else { int o = atomicAdd(&g_ovf_cnt, 1); g_ovf[o] = make_int3(r.x, c.x, __float_as_int(v.x)); }
        if (p1 < CAP) g_bucket[(size_t)r.y * CAP + p1] = make_int2(c.y, __float_as_int(v.y));
        else { int o = atomicAdd(&g_ovf_cnt, 1); g_ovf[o] = make_int3(r.y, c.y, __float_as_int(v.y)); }
        if (p2 < CAP) g_bucket[(size_t)r.z * CAP + p2] = make_int2(c.z, __float_as_int(v.z));
        else { int o = atomicAdd(&g_ovf_cnt, 1); g_ovf[o] = make_int3(r.z, c.z, __float_as_int(v.z)); }
        if (p3 < CAP) g_bucket[(size_t)r.w * CAP + p3] = make_int2(c.w, __float_as_int(v.w));
        else { int o = atomicAdd(&g_ovf_cnt, 1); g_ovf[o] = make_int3(r.w, c.w, __float_as_int(v.w)); }
    }
}

// ---------------------------------------------------------------------------
// Pull: 2 rows per warp, 16 lanes per row, 4 features (8B fp16) per lane.
// Per edge the 16-lane group reads 128B = ONE L2 line.
// fp32 accumulate, plain float4 store (bias fused, no atomics).
// Each half-warp zeroes its row's cursor after reading (invariant restore).
// ---------------------------------------------------------------------------
__global__ __launch_bounds__(256)
void pull_kernel(const float* __restrict__ bias, float* __restrict__ out) {
    int warp = (blockIdx.x * 256 + threadIdx.x) >> 5;
    if (warp >= NN / 2) return;
    int lane = threadIdx.x & 31;
    int half = lane >> 4;                // 0 or 1
    int sub  = lane & 15;                // 0..15

    const int row = warp * 2 + half;
    int len = g_cursor[row];
    __syncwarp();
    if (sub == 0) g_cursor[row] = 0;     // restore invariant (one writer/row)
    len = len < CAP ? len : CAP;

    const int lenm  = max(len, __shfl_xor_sync(0xffffffffu, len, 16));
    const int2* __restrict__ plist = g_bucket + (size_t)row * CAP;
    const int fo = sub * 4;
    const int hb = half << 4;

    float4 acc = *(const float4*)&bias[fo];

    for (int base = 0; base < lenm; base += 16) {
        int m  = len - base;
        int mm = lenm - base; mm = mm < 16 ? mm : 16;
        int2 p = make_int2(0, 0);
        if (sub < m) p = plist[base + sub];

        int j = 0;
        for (; j + 8 <= mm; j += 8) {
            int cc[8];
            uint2 rr[8];
            float vv[8];
#pragma unroll
            for (int k = 0; k < 8; k++)
                cc[k] = __shfl_sync(0xffffffffu, p.x, hb + j + k);
#pragma unroll
            for (int k = 0; k < 8; k++)
                rr[k] = *(const uint2*)&g_support_h[(size_t)cc[k] * OUTF + fo];
#pragma unroll
            for (int k = 0; k < 8; k++)
                vv[k] = __int_as_float(__shfl_sync(0xffffffffu, p.y, hb + j + k));
#pragma unroll
            for (int k = 0; k < 8; k++) {
                float2 a = __half22float2(*(__half2*)&rr[k].x);
                float2 b = __half22float2(*(__half2*)&rr[k].y);
                acc.x += a.x * vv[k]; acc.y += a.y * vv[k];
                acc.z += b.x * vv[k]; acc.w += b.y * vv[k];
            }
        }
        for (; j + 4 <= mm; j += 4) {
            int cc[4];
            uint2 rr[4];
            float vv[4];
#pragma unroll
            for (int k = 0; k < 4; k++)
                cc[k] = __shfl_sync(0xffffffffu, p.x, hb + j + k);
#pragma unroll
            for (int k = 0; k < 4; k++)
                rr[k] = *(const uint2*)&g_support_h[(size_t)cc[k] * OUTF + fo];
#pragma unroll
            for (int k = 0; k < 4; k++)
                vv[k] = __int_as_float(__shfl_sync(0xffffffffu, p.y, hb + j + k));
#pragma unroll
            for (int k = 0; k < 4; k++) {
                float2 a = __half22float2(*(__half2*)&rr[k].x);
                float2 b = __half22float2(*(__half2*)&rr[k].y);
                acc.x += a.x * vv[k]; acc.y += a.y * vv[k];
                acc.z += b.x * vv[k]; acc.w += b.y * vv[k];
            }
        }
        for (; j < mm; j++) {
            int   c = __shfl_sync(0xffffffffu, p.x, hb + j);
            float v = __int_as_float(__shfl_sync(0xffffffffu, p.y, hb + j));
            uint2 rv = *(const uint2*)&g_support_h[(size_t)c * OUTF + fo];
            float2 a = __half22float2(*(__half2*)&rv.x);
            float2 b = __half22float2(*(__half2*)&rv.y);
            acc.x += a.x * v; acc.y += a.y * v; acc.z += b.x * v; acc.w += b.y * v;
        }
    }

    *(float4*)&out[(size_t)row * OUTF + fo] = acc;
}

// ---------------------------------------------------------------------------
// Overflow fixup: apply spilled edges (degree > CAP) with vector reductions.
// Few thousand edges at most; runs after pull's plain stores.
// ---------------------------------------------------------------------------
__global__ void ovf_kernel(float* __restrict__ out) {
    int cnt = g_ovf_cnt;
    int total = cnt * 16;
    for (int i = blockIdx.x * blockDim.x + threadIdx.x; i < total;
         i += gridDim.x * blockDim.x) {
        int e = i >> 4;
        int f = (i & 15) << 2;
        int3 t = g_ovf[e];
        float v = __int_as_float(t.z);
        uint2 rv = *(const uint2*)&g_support_h[(size_t)t.y * OUTF + f];
        float2 a = __half22float2(*(__half2*)&rv.x);
        float2 b = __half22float2(*(__half2*)&rv.y);
        float* dst = &out[(size_t)t.x * OUTF + f];
        asm volatile("red.global.add.v4.f32 [%0], {%1, %2, %3, %4};"
                     :: "l"(dst), "f"(a.x * v), "f"(a.y * v), "f"(b.x * v), "f"(b.y * v)
                     : "memory");
    }
}

// ---------------------------------------------------------------------------
extern "C" void kernel_launch(void* const* d_in, const int* in_sizes, int n_in,
                              void* d_out, int out_size) {
    const float* x     = (const float*)d_in[0];   // [100000,128]
    const float* w     = (const float*)d_in[1];   // [128,64]
    const float* bias  = (const float*)d_in[2];   // [64]
    const int*   erow  = (const int*)  d_in[3];   // [1.6M]
    const int*   ecol  = (const int*)  d_in[4];   // [1.6M]
    const float* evals = (const float*)d_in[5];   // [1.6M]
    float* out = (float*)d_out;                   // [100000,64]

    const int n = in_sizes[0] / INF_;             // 100000

    // support = X @ W (fp32 compute, fp16 store) + zero spill counter
    gemm_kernel<<<(n + 63) / 64, 256>>>(x, w, n);

    // Bucket edges by destination row (single pass, no scan)
    fill_kernel<<<(NE / 4 + 255) / 256, 256>>>((const int4*)erow, (const int4*)ecol,
                                               (const float4*)evals);

    // Pull: out[row] = bias + sum(support[col] * val); zeroes cursors
    {
        int warps = NN / 2;                        // 50000
        int blocks = (warps * 32 + 255) / 256;     // 6250
        pull_kernel<<<blocks, 256>>>(bias, out);
    }

    // Apply spilled edges (Poisson tail beyond CAP)
    ovf_kernel<<<64, 256>>>(out);
}